// round 3
// baseline (speedup 1.0000x reference)
#include <cuda_runtime.h>
#include <cuda_bf16.h>
#include <cstdint>
#include <cstddef>

// ---------------------------------------------------------------------------
// Problem constants
// ---------------------------------------------------------------------------
#define TOK   16384              // B*S tokens
#define KDIM  2048               // hidden (reduction dim for both GEMMs)
#define NQKV  3072               // 2048 Q + 512 K + 512 V
#define NOUT  2048

// GEMM tiling
#define BM 128
#define BN 256
#define BK 64                    // 64 bf16 = 128 B row
#define NCHUNK (KDIM / BK)       // 32

// smem stage layout: [Ah 16K][Al 16K][Bh 32K][Bl 32K]
#define OFF_AH 0
#define OFF_AL 16384
#define OFF_BH 32768
#define OFF_BL 65536
#define STAGE_BYTES 98304
#define SMEM_TOTAL (2 * STAGE_BYTES)      // 196608

// ---------------------------------------------------------------------------
// Device scratch (static allocation only)
// ---------------------------------------------------------------------------
__device__ __nv_bfloat16 g_Xhi [(size_t)TOK * KDIM];
__device__ __nv_bfloat16 g_Xlo [(size_t)TOK * KDIM];
__device__ __nv_bfloat16 g_W1hi[(size_t)NQKV * KDIM];
__device__ __nv_bfloat16 g_W1lo[(size_t)NQKV * KDIM];
__device__ __nv_bfloat16 g_Wohi[(size_t)NOUT * KDIM];
__device__ __nv_bfloat16 g_Wolo[(size_t)NOUT * KDIM];
__device__ float         g_b1  [NQKV];
__device__ float         g_QKV [(size_t)TOK * NQKV];
__device__ __nv_bfloat16 g_Athi[(size_t)TOK * KDIM];
__device__ __nv_bfloat16 g_Atlo[(size_t)TOK * KDIM];

// ---------------------------------------------------------------------------
// PTX helpers (arch-generic: cp.async + ldmatrix + mma.sync only)
// ---------------------------------------------------------------------------
__device__ __forceinline__ uint32_t smem_u32_of(const void* p) {
    uint32_t a;
    asm("{ .reg .u64 t; cvta.to.shared.u64 t, %1; cvt.u32.u64 %0, t; }"
        : "=r"(a) : "l"(p));
    return a;
}

#define SWZ(off) ((off) ^ (((off) >> 3) & 0x70))

#define CP_ASYNC16(dst, src) \
    asm volatile("cp.async.cg.shared.global [%0], [%1], 16;" \
        :: "r"((uint32_t)(dst)), "l"(src) : "memory")

#define CP_ASYNC_COMMIT() asm volatile("cp.async.commit_group;" ::: "memory")
#define CP_ASYNC_WAIT1()  asm volatile("cp.async.wait_group 1;" ::: "memory")
#define CP_ASYNC_WAIT0()  asm volatile("cp.async.wait_group 0;" ::: "memory")

__device__ __forceinline__ void ldsm4(uint32_t* r, uint32_t addr) {
    asm volatile("ldmatrix.sync.aligned.m8n8.x4.shared.b16 {%0,%1,%2,%3}, [%4];"
        : "=r"(r[0]), "=r"(r[1]), "=r"(r[2]), "=r"(r[3]) : "r"(addr));
}

__device__ __forceinline__ void mma16816(float* c, const uint32_t* a,
                                         uint32_t b0, uint32_t b1) {
    asm volatile(
        "mma.sync.aligned.m16n8k16.row.col.f32.bf16.bf16.f32 "
        "{%0,%1,%2,%3}, {%4,%5,%6,%7}, {%8,%9}, {%0,%1,%2,%3};"
        : "+f"(c[0]), "+f"(c[1]), "+f"(c[2]), "+f"(c[3])
        : "r"(a[0]), "r"(a[1]), "r"(a[2]), "r"(a[3]), "r"(b0), "r"(b1));
}

// ---------------------------------------------------------------------------
// GEMM: C[M,N] = Ah@Bh^T + Ah@Bl^T + Al@Bh^T + bias   (bf16x3, fp32 acc)
// A: [M, KDIM] bf16 row-major (hi/lo), B: [N, KDIM] bf16 row-major (hi/lo)
// grid: (N/BN, M/BM), 256 threads, 8 warps as 2(m) x 4(n), warp tile 64x64
// ---------------------------------------------------------------------------
__device__ __forceinline__ void load_chunk(
    uint32_t sbase,
    const __nv_bfloat16* __restrict__ Ah, const __nv_bfloat16* __restrict__ Al,
    const __nv_bfloat16* __restrict__ Bh, const __nv_bfloat16* __restrict__ Bl,
    int m0, int n0, int k0, int tid)
{
    // A tiles: 128 rows x 128B = 1024 x 16B units, 4 per thread
    #pragma unroll
    for (int j = 0; j < 4; j++) {
        int u  = tid + 256 * j;
        int r  = u >> 3;
        int cc = u & 7;
        uint32_t so = (uint32_t)(r * 128 + ((cc * 16) ^ ((r & 7) * 16)));
        size_t   go = (size_t)(m0 + r) * KDIM + k0 + cc * 8;
        CP_ASYNC16(sbase + OFF_AH + so, Ah + go);
        CP_ASYNC16(sbase + OFF_AL + so, Al + go);
    }
    // B tiles: 256 rows x 128B = 2048 x 16B units, 8 per thread
    #pragma unroll
    for (int j = 0; j < 8; j++) {
        int u  = tid + 256 * j;
        int r  = u >> 3;
        int cc = u & 7;
        uint32_t so = (uint32_t)(r * 128 + ((cc * 16) ^ ((r & 7) * 16)));
        size_t   go = (size_t)(n0 + r) * KDIM + k0 + cc * 8;
        CP_ASYNC16(sbase + OFF_BH + so, Bh + go);
        CP_ASYNC16(sbase + OFF_BL + so, Bl + go);
    }
}

extern __shared__ __align__(1024) char smem_buf[];

__global__ void __launch_bounds__(256, 1) gemm_bf16x3(
    const __nv_bfloat16* __restrict__ Ah, const __nv_bfloat16* __restrict__ Al,
    const __nv_bfloat16* __restrict__ Bh, const __nv_bfloat16* __restrict__ Bl,
    const float* __restrict__ bias, float* __restrict__ C, int N)
{
    const uint32_t sb   = smem_u32_of(smem_buf);
    const int tid  = threadIdx.x;
    const int lane = tid & 31;
    const int warp = tid >> 5;
    const int wm   = warp & 1;       // m offset 0/64
    const int wn   = warp >> 1;      // n offset 0/64/128/192
    const int m0   = blockIdx.y * BM;
    const int n0   = blockIdx.x * BN;

    // ldmatrix lane geometry (identical pattern for A and B, K-contiguous TN)
    const int ldrow  = (lane & 7) + ((lane >> 3) & 1) * 8;  // row within 16-tile
    const int khalf  = (lane >> 4) * 16;                    // 0 or 16 bytes
    const int xr     = (lane & 7) * 16;                     // swizzle XOR
    const uint32_t rowAbyte = (uint32_t)(ldrow + wm * 64) * 128;
    const uint32_t rowBbyte = (uint32_t)(ldrow + wn * 64) * 128;

    const uint32_t stage_base[2] = { sb, sb + STAGE_BYTES };

    float acc[4][8][4] = {};

    // prologue
    load_chunk(stage_base[0], Ah, Al, Bh, Bl, m0, n0, 0, tid);
    CP_ASYNC_COMMIT();

    for (int c = 0; c < NCHUNK; c++) {
        const int s = c & 1;
        if (c + 1 < NCHUNK) {
            load_chunk(stage_base[(c + 1) & 1], Ah, Al, Bh, Bl,
                       m0, n0, (c + 1) * BK, tid);
            CP_ASYNC_COMMIT();
            CP_ASYNC_WAIT1();
        } else {
            CP_ASYNC_WAIT0();
        }
        __syncthreads();

        const uint32_t aH = stage_base[s] + OFF_AH + rowAbyte;
        const uint32_t aL = stage_base[s] + OFF_AL + rowAbyte;
        const uint32_t bH = stage_base[s] + OFF_BH + rowBbyte;
        const uint32_t bL = stage_base[s] + OFF_BL + rowBbyte;

        #pragma unroll
        for (int k16 = 0; k16 < 4; k16++) {
            const uint32_t colb = (uint32_t)((k16 * 32 + khalf) ^ xr);
            uint32_t ah[4][4], al[4][4], bh[4][4], bl[4][4];
            #pragma unroll
            for (int mt = 0; mt < 4; mt++) {
                ldsm4(ah[mt], aH + mt * 2048 + colb);
                ldsm4(al[mt], aL + mt * 2048 + colb);
            }
            #pragma unroll
            for (int nt = 0; nt < 4; nt++) {
                ldsm4(bh[nt], bH + nt * 2048 + colb);
                ldsm4(bl[nt], bL + nt * 2048 + colb);
            }
            #pragma unroll
            for (int mt = 0; mt < 4; mt++) {
                #pragma unroll
                for (int n8 = 0; n8 < 8; n8++) {
                    const int nt = n8 >> 1, h = n8 & 1;
                    mma16816(acc[mt][n8], ah[mt], bh[nt][h], bh[nt][h + 2]);
                    mma16816(acc[mt][n8], ah[mt], bl[nt][h], bl[nt][h + 2]);
                    mma16816(acc[mt][n8], al[mt], bh[nt][h], bh[nt][h + 2]);
                }
            }
        }
        __syncthreads();
    }

    // epilogue: add bias, write fp32
    const int gr  = lane >> 2;
    const int cp2 = (lane & 3) * 2;
    #pragma unroll
    for (int n8 = 0; n8 < 8; n8++) {
        const int col = n0 + wn * 64 + n8 * 8 + cp2;
        const float2 bv = *(const float2*)(bias + col);
        #pragma unroll
        for (int mt = 0; mt < 4; mt++) {
            const int row = m0 + wm * 64 + mt * 16 + gr;
            float2 v0 = { acc[mt][n8][0] + bv.x, acc[mt][n8][1] + bv.y };
            float2 v1 = { acc[mt][n8][2] + bv.x, acc[mt][n8][3] + bv.y };
            *(float2*)(C + (size_t)row * N + col)       = v0;
            *(float2*)(C + (size_t)(row + 8) * N + col) = v1;
        }
    }
}

// ---------------------------------------------------------------------------
// fp32 -> (bf16 hi, bf16 lo) split, vectorized
// ---------------------------------------------------------------------------
__global__ void __launch_bounds__(256) split_fp32(
    const float* __restrict__ in,
    __nv_bfloat16* __restrict__ hi, __nv_bfloat16* __restrict__ lo, int n4)
{
    int i = blockIdx.x * blockDim.x + threadIdx.x;
    const int stride = gridDim.x * blockDim.x;
    for (; i < n4; i += stride) {
        float4 v = ((const float4*)in)[i];
        float f[4] = { v.x, v.y, v.z, v.w };
        unsigned short hs[4], ls[4];
        #pragma unroll
        for (int j = 0; j < 4; j++) {
            __nv_bfloat16 h = __float2bfloat16(f[j]);
            __nv_bfloat16 l = __float2bfloat16(f[j] - __bfloat162float(h));
            hs[j] = __bfloat16_as_ushort(h);
            ls[j] = __bfloat16_as_ushort(l);
        }
        uint2 uh, ul;
        uh.x = (uint32_t)hs[0] | ((uint32_t)hs[1] << 16);
        uh.y = (uint32_t)hs[2] | ((uint32_t)hs[3] << 16);
        ul.x = (uint32_t)ls[0] | ((uint32_t)ls[1] << 16);
        ul.y = (uint32_t)ls[2] | ((uint32_t)ls[3] << 16);
        ((uint2*)hi)[i] = uh;
        ((uint2*)lo)[i] = ul;
    }
}

// ---------------------------------------------------------------------------
// Per-token attention. One block per token; q,k,v = one 3072-wide row of QKV
// (cols 0..2047 Q 16 heads, 2048..2559 K 4 heads, 2560..3071 V 4 heads).
// For q head r: s[kv] = q_r . k_kv / sqrt(128); softmax over 4 kv heads;
// out_r = sum w[kv] * v_kv. Output written pre-split into bf16 hi/lo.
// ---------------------------------------------------------------------------
__global__ void __launch_bounds__(128) attn_kernel(
    const float* __restrict__ QKV,
    __nv_bfloat16* __restrict__ Ahi, __nv_bfloat16* __restrict__ Alo)
{
    __shared__ float ks[512], vs[512];
    const int tok  = blockIdx.x;
    const int tid  = threadIdx.x;
    const int lane = tid & 31;
    const int w    = tid >> 5;
    const float* base = QKV + (size_t)tok * NQKV;

    ((float4*)ks)[tid] = ((const float4*)(base + 2048))[tid];
    ((float4*)vs)[tid] = ((const float4*)(base + 2560))[tid];
    __syncthreads();

    const float inv = 0.08838834764831845f;   // 1/sqrt(128)
    #pragma unroll
    for (int i = 0; i < 4; i++) {
        const int r = w * 4 + i;               // q head index 0..15
        float4 q4 = ((const float4*)(base + r * 128))[lane];
        float s[4];
        #pragma unroll
        for (int kv = 0; kv < 4; kv++) {
            float4 k4 = ((const float4*)(ks + kv * 128))[lane];
            float p = q4.x * k4.x + q4.y * k4.y + q4.z * k4.z + q4.w * k4.w;
            #pragma unroll
            for (int o = 16; o; o >>= 1) p += __shfl_xor_sync(0xffffffffu, p, o);
            s[kv] = p * inv;
        }
        float m = fmaxf(fmaxf(s[0], s[1]), fmaxf(s[2], s[3]));
        float e0 = __expf(s[0] - m), e1 = __expf(s[1] - m);
        float e2 = __expf(s[2] - m), e3 = __expf(s[3] - m);
        float rs = 1.0f / (e0 + e1 + e2 + e3);
        float w0 = e0 * rs, w1 = e1 * rs, w2 = e2 * rs, w3 = e3 * rs;

        float4 v0 = ((const float4*)(vs +   0))[lane];
        float4 v1 = ((const float4*)(vs + 128))[lane];
        float4 v2 = ((const float4*)(vs + 256))[lane];
        float4 v3 = ((const float4*)(vs + 384))[lane];
        float f[4];
        f[0] = w0 * v0.x + w1 * v1.x + w2 * v2.x + w3 * v3.x;
        f[1] = w0 * v0.y + w1 * v1.y + w2 * v2.y + w3 * v3.y;
        f[2] = w0 * v0.z + w1 * v1.z + w2 * v2.z + w3 * v3.z;
        f[3] = w0 * v0.w + w1 * v1.w + w2 * v2.w + w3 * v3.w;

        unsigned short hs4[4], ls4[4];
        #pragma unroll
        for (int j = 0; j < 4; j++) {
            __nv_bfloat16 h = __float2bfloat16(f[j]);
            __nv_bfloat16 l = __float2bfloat16(f[j] - __bfloat162float(h));
            hs4[j] = __bfloat16_as_ushort(h);
            ls4[j] = __bfloat16_as_ushort(l);
        }
        uint2 uh, ul;
        uh.x = (uint32_t)hs4[0] | ((uint32_t)hs4[1] << 16);
        uh.y = (uint32_t)hs4[2] | ((uint32_t)hs4[3] << 16);
        ul.x = (uint32_t)ls4[0] | ((uint32_t)ls4[1] << 16);
        ul.y = (uint32_t)ls4[2] | ((uint32_t)ls4[3] << 16);
        const size_t idx = (size_t)tok * KDIM + r * 128 + lane * 4;
        *(uint2*)(Ahi + idx) = uh;
        *(uint2*)(Alo + idx) = ul;
    }
}

// ---------------------------------------------------------------------------
// Host launcher
// ---------------------------------------------------------------------------
extern "C" void kernel_launch(void* const* d_in, const int* in_sizes, int n_in,
                              void* d_out, int out_size)
{
    (void)in_sizes; (void)n_in; (void)out_size;
    const float* x  = (const float*)d_in[0];
    const float* Wq = (const float*)d_in[1];
    const float* bq = (const float*)d_in[2];
    const float* Wk = (const float*)d_in[3];
    const float* bk = (const float*)d_in[4];
    const float* Wv = (const float*)d_in[5];
    const float* bv = (const float*)d_in[6];
    const float* Wo = (const float*)d_in[7];
    const float* bo = (const float*)d_in[8];

    void *p_xh, *p_xl, *p_w1h, *p_w1l, *p_woh, *p_wol, *p_b1, *p_qkv, *p_ah, *p_al;
    cudaGetSymbolAddress(&p_xh,  g_Xhi);
    cudaGetSymbolAddress(&p_xl,  g_Xlo);
    cudaGetSymbolAddress(&p_w1h, g_W1hi);
    cudaGetSymbolAddress(&p_w1l, g_W1lo);
    cudaGetSymbolAddress(&p_woh, g_Wohi);
    cudaGetSymbolAddress(&p_wol, g_Wolo);
    cudaGetSymbolAddress(&p_b1,  g_b1);
    cudaGetSymbolAddress(&p_qkv, g_QKV);
    cudaGetSymbolAddress(&p_ah,  g_Athi);
    cudaGetSymbolAddress(&p_al,  g_Atlo);

    __nv_bfloat16* xh  = (__nv_bfloat16*)p_xh;
    __nv_bfloat16* xl  = (__nv_bfloat16*)p_xl;
    __nv_bfloat16* w1h = (__nv_bfloat16*)p_w1h;
    __nv_bfloat16* w1l = (__nv_bfloat16*)p_w1l;
    __nv_bfloat16* woh = (__nv_bfloat16*)p_woh;
    __nv_bfloat16* wol = (__nv_bfloat16*)p_wol;
    float*         b1  = (float*)p_b1;
    float*         qkv = (float*)p_qkv;
    __nv_bfloat16* ah  = (__nv_bfloat16*)p_ah;
    __nv_bfloat16* al  = (__nv_bfloat16*)p_al;

    // fp32 -> bf16 hi/lo splits; QKV weights packed into one [3072, 2048] buffer
    split_fp32<<<2048, 256>>>(x,  xh, xl, TOK * KDIM / 4);
    split_fp32<<<256, 256>>>(Wq, w1h,               w1l,               2048 * 2048 / 4);
    split_fp32<<<64,  256>>>(Wk, w1h + 2048 * 2048, w1l + 2048 * 2048, 512 * 2048 / 4);
    split_fp32<<<64,  256>>>(Wv, w1h + 2560 * 2048, w1l + 2560 * 2048, 512 * 2048 / 4);
    split_fp32<<<256, 256>>>(Wo, woh, wol, 2048 * 2048 / 4);
    cudaMemcpyAsync(b1,        bq, 2048 * sizeof(float), cudaMemcpyDeviceToDevice);
    cudaMemcpyAsync(b1 + 2048, bk,  512 * sizeof(float), cudaMemcpyDeviceToDevice);
    cudaMemcpyAsync(b1 + 2560, bv,  512 * sizeof(float), cudaMemcpyDeviceToDevice);

    cudaFuncSetAttribute(gemm_bf16x3,
                         cudaFuncAttributeMaxDynamicSharedMemorySize, SMEM_TOTAL);

    // GEMM1: QKV = X @ W1^T + b1
    gemm_bf16x3<<<dim3(NQKV / BN, TOK / BM), 256, SMEM_TOTAL>>>(
        xh, xl, w1h, w1l, b1, qkv, NQKV);

    // per-token attention -> hi/lo split output
    attn_kernel<<<TOK, 128>>>(qkv, ah, al);

    // GEMM2: out = Att @ Wo^T + bo
    gemm_bf16x3<<<dim3(NOUT / BN, TOK / BM), 256, SMEM_TOTAL>>>(
        ah, al, woh, wol, bo, (float*)d_out, NOUT);
}

// round 5
// speedup vs baseline: 1.0419x; 1.0419x over previous
#include <cuda_runtime.h>
#include <cuda_bf16.h>
#include <cstdint>
#include <cstddef>

// ---------------------------------------------------------------------------
// Problem constants
// ---------------------------------------------------------------------------
#define TOK   16384              // B*S tokens
#define KDIM  2048               // hidden (reduction dim for both GEMMs)
#define NQKV  3072               // 2048 Q + 512 K + 512 V
#define NOUT  2048

// GEMM tiling
#define BM 128
#define BN 256
#define BK 64                    // 64 bf16 = 128 B row
#define NCHUNK (KDIM / BK)       // 32

// smem stage layout: [Ah 16K][Al 16K][Bh 32K][Bl 32K]
#define OFF_AH 0
#define OFF_AL 16384
#define OFF_BH 32768
#define OFF_BL 65536
#define STAGE_BYTES 98304
#define SMEM_TOTAL (2 * STAGE_BYTES)      // 196608

// ---------------------------------------------------------------------------
// Device scratch (static allocation only)
// ---------------------------------------------------------------------------
__device__ __nv_bfloat16 g_Xhi [(size_t)TOK * KDIM];
__device__ __nv_bfloat16 g_Xlo [(size_t)TOK * KDIM];
__device__ __nv_bfloat16 g_W1hi[(size_t)NQKV * KDIM];
__device__ __nv_bfloat16 g_W1lo[(size_t)NQKV * KDIM];
__device__ __nv_bfloat16 g_Wohi[(size_t)NOUT * KDIM];
__device__ __nv_bfloat16 g_Wolo[(size_t)NOUT * KDIM];
__device__ float         g_b1  [NQKV];
__device__ float         g_QKV [(size_t)TOK * NQKV];
__device__ __nv_bfloat16 g_Athi[(size_t)TOK * KDIM];
__device__ __nv_bfloat16 g_Atlo[(size_t)TOK * KDIM];

// ---------------------------------------------------------------------------
// PTX helpers (arch-generic: cp.async + ldmatrix + mma.sync only)
// ---------------------------------------------------------------------------
__device__ __forceinline__ uint32_t smem_u32_of(const void* p) {
    uint32_t a;
    asm("{ .reg .u64 t; cvta.to.shared.u64 t, %1; cvt.u32.u64 %0, t; }"
        : "=r"(a) : "l"(p));
    return a;
}

#define CP_ASYNC16(dst, src) \
    asm volatile("cp.async.cg.shared.global [%0], [%1], 16;" \
        :: "r"((uint32_t)(dst)), "l"(src) : "memory")

#define CP_ASYNC_COMMIT() asm volatile("cp.async.commit_group;" ::: "memory")
#define CP_ASYNC_WAIT0()  asm volatile("cp.async.wait_group 0;" ::: "memory")

__device__ __forceinline__ void ldsm4(uint32_t* r, uint32_t addr) {
    asm volatile("ldmatrix.sync.aligned.m8n8.x4.shared.b16 {%0,%1,%2,%3}, [%4];"
        : "=r"(r[0]), "=r"(r[1]), "=r"(r[2]), "=r"(r[3]) : "r"(addr));
}

__device__ __forceinline__ void mma16816(float* c, const uint32_t* a,
                                         uint32_t b0, uint32_t b1) {
    asm volatile(
        "mma.sync.aligned.m16n8k16.row.col.f32.bf16.bf16.f32 "
        "{%0,%1,%2,%3}, {%4,%5,%6,%7}, {%8,%9}, {%0,%1,%2,%3};"
        : "+f"(c[0]), "+f"(c[1]), "+f"(c[2]), "+f"(c[3])
        : "r"(a[0]), "r"(a[1]), "r"(a[2]), "r"(a[3]), "r"(b0), "r"(b1));
}

// ---------------------------------------------------------------------------
// GEMM: C[M,N] = Ah@Bh^T + Ah@Bl^T + Al@Bh^T + bias   (bf16x3, fp32 acc)
// A: [M, KDIM] bf16 row-major (hi/lo), B: [N, KDIM] bf16 row-major (hi/lo)
// grid: (N/BN, M/BM), 256 threads, 8 warps as 2(m) x 4(n), warp tile 64x64
// ---------------------------------------------------------------------------
__device__ __forceinline__ void load_chunk(
    uint32_t sbase,
    const __nv_bfloat16* __restrict__ Ah, const __nv_bfloat16* __restrict__ Al,
    const __nv_bfloat16* __restrict__ Bh, const __nv_bfloat16* __restrict__ Bl,
    int m0, int n0, int k0, int tid)
{
    // A tiles: 128 rows x 128B = 1024 x 16B units, 4 per thread
    #pragma unroll
    for (int j = 0; j < 4; j++) {
        int u  = tid + 256 * j;
        int r  = u >> 3;
        int cc = u & 7;
        uint32_t so = (uint32_t)(r * 128 + ((cc * 16) ^ ((r & 7) * 16)));
        size_t   go = (size_t)(m0 + r) * KDIM + k0 + cc * 8;
        CP_ASYNC16(sbase + OFF_AH + so, Ah + go);
        CP_ASYNC16(sbase + OFF_AL + so, Al + go);
    }
    // B tiles: 256 rows x 128B = 2048 x 16B units, 8 per thread
    #pragma unroll
    for (int j = 0; j < 8; j++) {
        int u  = tid + 256 * j;
        int r  = u >> 3;
        int cc = u & 7;
        uint32_t so = (uint32_t)(r * 128 + ((cc * 16) ^ ((r & 7) * 16)));
        size_t   go = (size_t)(n0 + r) * KDIM + k0 + cc * 8;
        CP_ASYNC16(sbase + OFF_BH + so, Bh + go);
        CP_ASYNC16(sbase + OFF_BL + so, Bl + go);
    }
}

extern __shared__ __align__(1024) char smem_buf[];

__global__ void __launch_bounds__(256, 1) gemm_bf16x3(
    const __nv_bfloat16* __restrict__ Ah, const __nv_bfloat16* __restrict__ Al,
    const __nv_bfloat16* __restrict__ Bh, const __nv_bfloat16* __restrict__ Bl,
    const float* __restrict__ bias, float* __restrict__ C, int N)
{
    const uint32_t sb   = smem_u32_of(smem_buf);
    const int tid  = threadIdx.x;
    const int lane = tid & 31;
    const int warp = tid >> 5;
    const int wm   = warp & 1;       // m offset 0/64
    const int wn   = warp >> 1;      // n offset 0/64/128/192
    const int m0   = blockIdx.y * BM;
    const int n0   = blockIdx.x * BN;

    // ldmatrix lane geometry (identical pattern for A and B, K-contiguous TN)
    const int ldrow  = (lane & 7) + ((lane >> 3) & 1) * 8;  // row within 16-tile
    const int khalf  = (lane >> 4) * 16;                    // 0 or 16 bytes
    const int xr     = (lane & 7) * 16;                     // swizzle XOR
    const uint32_t rowAbyte = (uint32_t)(ldrow + wm * 64) * 128;
    const uint32_t rowBbyte = (uint32_t)(ldrow + wn * 64) * 128;

    const uint32_t stage_base[2] = { sb, sb + STAGE_BYTES };

    float acc[4][8][4] = {};

    // prologue: chunk 0 -> stage 0
    load_chunk(stage_base[0], Ah, Al, Bh, Bl, m0, n0, 0, tid);
    CP_ASYNC_COMMIT();

    for (int c = 0; c < NCHUNK; c++) {
        // 1) my cp.async groups (chunk c is the only outstanding one) complete
        CP_ASYNC_WAIT0();
        // 2) barrier AFTER the wait: chunk c now visible to every warp, and
        //    every warp has finished computing chunk c-1, so the stage the
        //    next load overwrites is free. One barrier serves both duties.
        __syncthreads();
        // 3) kick off chunk c+1 (overlaps with compute of chunk c)
        if (c + 1 < NCHUNK) {
            load_chunk(stage_base[(c + 1) & 1], Ah, Al, Bh, Bl,
                       m0, n0, (c + 1) * BK, tid);
            CP_ASYNC_COMMIT();
        }

        const int s = c & 1;
        const uint32_t aH = stage_base[s] + OFF_AH + rowAbyte;
        const uint32_t aL = stage_base[s] + OFF_AL + rowAbyte;
        const uint32_t bH = stage_base[s] + OFF_BH + rowBbyte;
        const uint32_t bL = stage_base[s] + OFF_BL + rowBbyte;

        #pragma unroll
        for (int k16 = 0; k16 < 4; k16++) {
            const uint32_t colb = (uint32_t)((k16 * 32 + khalf) ^ xr);
            uint32_t ah[4][4], al[4][4];
            #pragma unroll
            for (int mt = 0; mt < 4; mt++) {
                ldsm4(ah[mt], aH + mt * 2048 + colb);
                ldsm4(al[mt], aL + mt * 2048 + colb);
            }
            // hi-B pass: Ah*Bh then Al*Bh (dependent pairs spaced by 8 MMAs)
            #pragma unroll
            for (int nt = 0; nt < 4; nt++) {
                uint32_t b[4];
                ldsm4(b, bH + nt * 2048 + colb);
                #pragma unroll
                for (int mt = 0; mt < 4; mt++) {
                    mma16816(acc[mt][2 * nt],     ah[mt], b[0], b[2]);
                    mma16816(acc[mt][2 * nt + 1], ah[mt], b[1], b[3]);
                }
                #pragma unroll
                for (int mt = 0; mt < 4; mt++) {
                    mma16816(acc[mt][2 * nt],     al[mt], b[0], b[2]);
                    mma16816(acc[mt][2 * nt + 1], al[mt], b[1], b[3]);
                }
            }
            // lo-B pass: Ah*Bl
            #pragma unroll
            for (int nt = 0; nt < 4; nt++) {
                uint32_t b[4];
                ldsm4(b, bL + nt * 2048 + colb);
                #pragma unroll
                for (int mt = 0; mt < 4; mt++) {
                    mma16816(acc[mt][2 * nt],     ah[mt], b[0], b[2]);
                    mma16816(acc[mt][2 * nt + 1], ah[mt], b[1], b[3]);
                }
            }
        }
    }

    // epilogue: add bias, write fp32
    const int gr  = lane >> 2;
    const int cp2 = (lane & 3) * 2;
    #pragma unroll
    for (int n8 = 0; n8 < 8; n8++) {
        const int col = n0 + wn * 64 + n8 * 8 + cp2;
        const float2 bv = *(const float2*)(bias + col);
        #pragma unroll
        for (int mt = 0; mt < 4; mt++) {
            const int row = m0 + wm * 64 + mt * 16 + gr;
            float2 v0 = { acc[mt][n8][0] + bv.x, acc[mt][n8][1] + bv.y };
            float2 v1 = { acc[mt][n8][2] + bv.x, acc[mt][n8][3] + bv.y };
            *(float2*)(C + (size_t)row * N + col)       = v0;
            *(float2*)(C + (size_t)(row + 8) * N + col) = v1;
        }
    }
}

// ---------------------------------------------------------------------------
// fp32 -> (bf16 hi, bf16 lo) split, vectorized
// ---------------------------------------------------------------------------
__device__ __forceinline__ void split4(const float4 v, uint2* uh, uint2* ul) {
    float f[4] = { v.x, v.y, v.z, v.w };
    unsigned short hs[4], ls[4];
    #pragma unroll
    for (int j = 0; j < 4; j++) {
        __nv_bfloat16 h = __float2bfloat16(f[j]);
        __nv_bfloat16 l = __float2bfloat16(f[j] - __bfloat162float(h));
        hs[j] = __bfloat16_as_ushort(h);
        ls[j] = __bfloat16_as_ushort(l);
    }
    uh->x = (uint32_t)hs[0] | ((uint32_t)hs[1] << 16);
    uh->y = (uint32_t)hs[2] | ((uint32_t)hs[3] << 16);
    ul->x = (uint32_t)ls[0] | ((uint32_t)ls[1] << 16);
    ul->y = (uint32_t)ls[2] | ((uint32_t)ls[3] << 16);
}

__global__ void __launch_bounds__(256) split_fp32(
    const float* __restrict__ in,
    __nv_bfloat16* __restrict__ hi, __nv_bfloat16* __restrict__ lo, int n4)
{
    int i = blockIdx.x * blockDim.x + threadIdx.x;
    const int stride = gridDim.x * blockDim.x;
    for (; i < n4; i += stride) {
        uint2 uh, ul;
        split4(((const float4*)in)[i], &uh, &ul);
        ((uint2*)hi)[i] = uh;
        ((uint2*)lo)[i] = ul;
    }
}

// Fused split of Wq/Wk/Wv into packed [3072,2048] hi/lo + bias concat.
__global__ void __launch_bounds__(256) split_w1_fused(
    const float* __restrict__ Wq, const float* __restrict__ Wk,
    const float* __restrict__ Wv,
    const float* __restrict__ bq, const float* __restrict__ bk,
    const float* __restrict__ bv,
    __nv_bfloat16* __restrict__ hi, __nv_bfloat16* __restrict__ lo,
    float* __restrict__ b1)
{
    const int tid0 = blockIdx.x * blockDim.x + threadIdx.x;
    // bias concat: 3072 floats = 768 float4
    if (tid0 < 768) {
        float4 v;
        if      (tid0 < 512) v = ((const float4*)bq)[tid0];
        else if (tid0 < 640) v = ((const float4*)bk)[tid0 - 512];
        else                 v = ((const float4*)bv)[tid0 - 640];
        ((float4*)b1)[tid0] = v;
    }
    const int n4 = NQKV * (KDIM / 4);      // rows x 512 float4 per row
    const int stride = gridDim.x * blockDim.x;
    for (int i = tid0; i < n4; i += stride) {
        const int row = i >> 9;            // /512
        const int col = i & 511;
        float4 v;
        if      (row < 2048) v = ((const float4*)Wq)[(size_t)row * 512 + col];
        else if (row < 2560) v = ((const float4*)Wk)[(size_t)(row - 2048) * 512 + col];
        else                 v = ((const float4*)Wv)[(size_t)(row - 2560) * 512 + col];
        uint2 uh, ul;
        split4(v, &uh, &ul);
        ((uint2*)hi)[i] = uh;
        ((uint2*)lo)[i] = ul;
    }
}

// ---------------------------------------------------------------------------
// Per-token attention. One block per token; q,k,v = one 3072-wide row of QKV
// (cols 0..2047 Q 16 heads, 2048..2559 K 4 heads, 2560..3071 V 4 heads).
// For q head r: s[kv] = q_r . k_kv / sqrt(128); softmax over 4 kv heads;
// out_r = sum w[kv] * v_kv. Output written pre-split into bf16 hi/lo.
// ---------------------------------------------------------------------------
__global__ void __launch_bounds__(128) attn_kernel(
    const float* __restrict__ QKV,
    __nv_bfloat16* __restrict__ Ahi, __nv_bfloat16* __restrict__ Alo)
{
    __shared__ float ks[512], vs[512];
    const int tok  = blockIdx.x;
    const int tid  = threadIdx.x;
    const int lane = tid & 31;
    const int w    = tid >> 5;
    const float* base = QKV + (size_t)tok * NQKV;

    ((float4*)ks)[tid] = ((const float4*)(base + 2048))[tid];
    ((float4*)vs)[tid] = ((const float4*)(base + 2560))[tid];
    __syncthreads();

    const float inv = 0.08838834764831845f;   // 1/sqrt(128)
    #pragma unroll
    for (int i = 0; i < 4; i++) {
        const int r = w * 4 + i;               // q head index 0..15
        float4 q4 = ((const float4*)(base + r * 128))[lane];
        float s[4];
        #pragma unroll
        for (int kv = 0; kv < 4; kv++) {
            float4 k4 = ((const float4*)(ks + kv * 128))[lane];
            float p = q4.x * k4.x + q4.y * k4.y + q4.z * k4.z + q4.w * k4.w;
            #pragma unroll
            for (int o = 16; o; o >>= 1) p += __shfl_xor_sync(0xffffffffu, p, o);
            s[kv] = p * inv;
        }
        float m = fmaxf(fmaxf(s[0], s[1]), fmaxf(s[2], s[3]));
        float e0 = __expf(s[0] - m), e1 = __expf(s[1] - m);
        float e2 = __expf(s[2] - m), e3 = __expf(s[3] - m);
        float rs = 1.0f / (e0 + e1 + e2 + e3);
        float w0 = e0 * rs, w1 = e1 * rs, w2 = e2 * rs, w3 = e3 * rs;

        float4 v0 = ((const float4*)(vs +   0))[lane];
        float4 v1 = ((const float4*)(vs + 128))[lane];
        float4 v2 = ((const float4*)(vs + 256))[lane];
        float4 v3 = ((const float4*)(vs + 384))[lane];
        float4 f;
        f.x = w0 * v0.x + w1 * v1.x + w2 * v2.x + w3 * v3.x;
        f.y = w0 * v0.y + w1 * v1.y + w2 * v2.y + w3 * v3.y;
        f.z = w0 * v0.z + w1 * v1.z + w2 * v2.z + w3 * v3.z;
        f.w = w0 * v0.w + w1 * v1.w + w2 * v2.w + w3 * v3.w;

        uint2 uh, ul;
        split4(f, &uh, &ul);
        const size_t idx = (size_t)tok * KDIM + r * 128 + lane * 4;
        *(uint2*)(Ahi + idx) = uh;
        *(uint2*)(Alo + idx) = ul;
    }
}

// ---------------------------------------------------------------------------
// Host launcher
// ---------------------------------------------------------------------------
extern "C" void kernel_launch(void* const* d_in, const int* in_sizes, int n_in,
                              void* d_out, int out_size)
{
    (void)in_sizes; (void)n_in; (void)out_size;
    const float* x  = (const float*)d_in[0];
    const float* Wq = (const float*)d_in[1];
    const float* bq = (const float*)d_in[2];
    const float* Wk = (const float*)d_in[3];
    const float* bk = (const float*)d_in[4];
    const float* Wv = (const float*)d_in[5];
    const float* bv = (const float*)d_in[6];
    const float* Wo = (const float*)d_in[7];
    const float* bo = (const float*)d_in[8];

    void *p_xh, *p_xl, *p_w1h, *p_w1l, *p_woh, *p_wol, *p_b1, *p_qkv, *p_ah, *p_al;
    cudaGetSymbolAddress(&p_xh,  g_Xhi);
    cudaGetSymbolAddress(&p_xl,  g_Xlo);
    cudaGetSymbolAddress(&p_w1h, g_W1hi);
    cudaGetSymbolAddress(&p_w1l, g_W1lo);
    cudaGetSymbolAddress(&p_woh, g_Wohi);
    cudaGetSymbolAddress(&p_wol, g_Wolo);
    cudaGetSymbolAddress(&p_b1,  g_b1);
    cudaGetSymbolAddress(&p_qkv, g_QKV);
    cudaGetSymbolAddress(&p_ah,  g_Athi);
    cudaGetSymbolAddress(&p_al,  g_Atlo);

    __nv_bfloat16* xh  = (__nv_bfloat16*)p_xh;
    __nv_bfloat16* xl  = (__nv_bfloat16*)p_xl;
    __nv_bfloat16* w1h = (__nv_bfloat16*)p_w1h;
    __nv_bfloat16* w1l = (__nv_bfloat16*)p_w1l;
    __nv_bfloat16* woh = (__nv_bfloat16*)p_woh;
    __nv_bfloat16* wol = (__nv_bfloat16*)p_wol;
    float*         b1  = (float*)p_b1;
    float*         qkv = (float*)p_qkv;
    __nv_bfloat16* ah  = (__nv_bfloat16*)p_ah;
    __nv_bfloat16* al  = (__nv_bfloat16*)p_al;

    // launch order (5 launches before gemm2 so ncu -s 5 captures gemm2):
    // 1 split_x, 2 split_w1_fused, 3 split_wo, 4 gemm1, 5 attn, 6 gemm2
    split_fp32<<<2048, 256>>>(x, xh, xl, TOK * KDIM / 4);
    split_w1_fused<<<512, 256>>>(Wq, Wk, Wv, bq, bk, bv, w1h, w1l, b1);
    split_fp32<<<256, 256>>>(Wo, woh, wol, 2048 * 2048 / 4);

    cudaFuncSetAttribute(gemm_bf16x3,
                         cudaFuncAttributeMaxDynamicSharedMemorySize, SMEM_TOTAL);

    // GEMM1: QKV = X @ W1^T + b1
    gemm_bf16x3<<<dim3(NQKV / BN, TOK / BM), 256, SMEM_TOTAL>>>(
        xh, xl, w1h, w1l, b1, qkv, NQKV);

    // per-token attention -> hi/lo split output
    attn_kernel<<<TOK, 128>>>(qkv, ah, al);

    // GEMM2: out = Att @ Wo^T + bo
    gemm_bf16x3<<<dim3(NOUT / BN, TOK / BM), 256, SMEM_TOTAL>>>(
        ah, al, woh, wol, bo, (float*)d_out, NOUT);
}

// round 6
// speedup vs baseline: 1.4696x; 1.4106x over previous
#include <cuda_runtime.h>
#include <cuda_fp16.h>
#include <cstdint>
#include <cstddef>

// ---------------------------------------------------------------------------
// Problem constants
// ---------------------------------------------------------------------------
#define TOK   16384              // B*S tokens
#define KDIM  2048               // hidden (reduction dim for both GEMMs)
#define NQKV  3072               // 2048 Q + 512 K + 512 V
#define NOUT  2048

// GEMM tiling
#define BM 128
#define BN 256
#define BK 64                    // 64 fp16 = 128 B row
#define NCHUNK (KDIM / BK)       // 32
#define NSTAGE 3

// smem stage layout: [Ah 16K][Al 16K][Bh 32K]
#define OFF_AH 0
#define OFF_AL 16384
#define OFF_BH 32768
#define STAGE_BYTES 65536
#define SMEM_TOTAL (NSTAGE * STAGE_BYTES)   // 196608

// ---------------------------------------------------------------------------
// Device scratch (static allocation only)
// ---------------------------------------------------------------------------
__device__ __half g_Xhi [(size_t)TOK * KDIM];
__device__ __half g_Xlo [(size_t)TOK * KDIM];
__device__ __half g_W1hi[(size_t)NQKV * KDIM];
__device__ __half g_Wohi[(size_t)NOUT * KDIM];
__device__ float  g_b1  [NQKV];
__device__ float  g_QKV [(size_t)TOK * NQKV];
__device__ __half g_Athi[(size_t)TOK * KDIM];
__device__ __half g_Atlo[(size_t)TOK * KDIM];

// ---------------------------------------------------------------------------
// PTX helpers (arch-generic: cp.async + ldmatrix + mma.sync only)
// ---------------------------------------------------------------------------
__device__ __forceinline__ uint32_t smem_u32_of(const void* p) {
    uint32_t a;
    asm("{ .reg .u64 t; cvta.to.shared.u64 t, %1; cvt.u32.u64 %0, t; }"
        : "=r"(a) : "l"(p));
    return a;
}

#define CP_ASYNC16(dst, src) \
    asm volatile("cp.async.cg.shared.global [%0], [%1], 16;" \
        :: "r"((uint32_t)(dst)), "l"(src) : "memory")

#define CP_ASYNC_COMMIT() asm volatile("cp.async.commit_group;" ::: "memory")
#define CP_ASYNC_WAIT1()  asm volatile("cp.async.wait_group 1;" ::: "memory")
#define CP_ASYNC_WAIT0()  asm volatile("cp.async.wait_group 0;" ::: "memory")

__device__ __forceinline__ void ldsm4(uint32_t* r, uint32_t addr) {
    asm volatile("ldmatrix.sync.aligned.m8n8.x4.shared.b16 {%0,%1,%2,%3}, [%4];"
        : "=r"(r[0]), "=r"(r[1]), "=r"(r[2]), "=r"(r[3]) : "r"(addr));
}

__device__ __forceinline__ void mma16816(float* c, const uint32_t* a,
                                         uint32_t b0, uint32_t b1) {
    asm volatile(
        "mma.sync.aligned.m16n8k16.row.col.f32.f16.f16.f32 "
        "{%0,%1,%2,%3}, {%4,%5,%6,%7}, {%8,%9}, {%0,%1,%2,%3};"
        : "+f"(c[0]), "+f"(c[1]), "+f"(c[2]), "+f"(c[3])
        : "r"(a[0]), "r"(a[1]), "r"(a[2]), "r"(a[3]), "r"(b0), "r"(b1));
}

// ---------------------------------------------------------------------------
// GEMM: C[M,N] = (Ah + Al) @ Bh^T + bias     (fp16 2-term, fp32 accum)
//   Ah/Al: hi/lo fp16 split of fp32 A  ->  A is applied EXACTLY;
//   the only error is B's fp16 quantization (~3.5e-4 relative).
// A: [M, KDIM] fp16 row-major (hi/lo), B: [N, KDIM] fp16 row-major (hi)
// grid: (N/BN, M/BM), 256 threads, 8 warps as 2(m) x 4(n), warp tile 64x64
// ---------------------------------------------------------------------------
__device__ __forceinline__ void load_chunk(
    uint32_t sbase,
    const __half* __restrict__ Ah, const __half* __restrict__ Al,
    const __half* __restrict__ Bh,
    int m0, int n0, int k0, int tid)
{
    // A tiles: 128 rows x 128B = 1024 x 16B units, 4 per thread (hi+lo)
    #pragma unroll
    for (int j = 0; j < 4; j++) {
        int u  = tid + 256 * j;
        int r  = u >> 3;
        int cc = u & 7;
        uint32_t so = (uint32_t)(r * 128 + ((cc * 16) ^ ((r & 7) * 16)));
        size_t   go = (size_t)(m0 + r) * KDIM + k0 + cc * 8;
        CP_ASYNC16(sbase + OFF_AH + so, Ah + go);
        CP_ASYNC16(sbase + OFF_AL + so, Al + go);
    }
    // B tile: 256 rows x 128B = 2048 x 16B units, 8 per thread (hi only)
    #pragma unroll
    for (int j = 0; j < 8; j++) {
        int u  = tid + 256 * j;
        int r  = u >> 3;
        int cc = u & 7;
        uint32_t so = (uint32_t)(r * 128 + ((cc * 16) ^ ((r & 7) * 16)));
        size_t   go = (size_t)(n0 + r) * KDIM + k0 + cc * 8;
        CP_ASYNC16(sbase + OFF_BH + so, Bh + go);
    }
}

extern __shared__ __align__(1024) char smem_buf[];

__global__ void __launch_bounds__(256, 1) gemm_fp16x2(
    const __half* __restrict__ Ah, const __half* __restrict__ Al,
    const __half* __restrict__ Bh,
    const float* __restrict__ bias, float* __restrict__ C, int N)
{
    const uint32_t sb   = smem_u32_of(smem_buf);
    const int tid  = threadIdx.x;
    const int lane = tid & 31;
    const int warp = tid >> 5;
    const int wm   = warp & 1;       // m offset 0/64
    const int wn   = warp >> 1;      // n offset 0/64/128/192
    const int m0   = blockIdx.y * BM;
    const int n0   = blockIdx.x * BN;

    // ldmatrix lane geometry (identical pattern for A and B, K-contiguous TN)
    const int ldrow  = (lane & 7) + ((lane >> 3) & 1) * 8;  // row within 16-tile
    const int khalf  = (lane >> 4) * 16;                    // 0 or 16 bytes
    const int xr     = (lane & 7) * 16;                     // swizzle XOR
    const uint32_t rowAbyte = (uint32_t)(ldrow + wm * 64) * 128;
    const uint32_t rowBbyte = (uint32_t)(ldrow + wn * 64) * 128;

    float acc[4][8][4] = {};

    // prologue: chunks 0,1 -> stages 0,1 (one commit group per chunk)
    load_chunk(sb, Ah, Al, Bh, m0, n0, 0, tid);
    CP_ASYNC_COMMIT();
    load_chunk(sb + STAGE_BYTES, Ah, Al, Bh, m0, n0, BK, tid);
    CP_ASYNC_COMMIT();

    int stage = 0;                        // stage of chunk c
    for (int c = 0; c < NCHUNK; c++) {
        // 1) ensure chunk c's group is complete (newest outstanding = c+1)
        if (c + 1 < NCHUNK) CP_ASYNC_WAIT1();
        else                CP_ASYNC_WAIT0();
        // 2) barrier AFTER wait: chunk c visible to all warps; all warps done
        //    computing chunk c-1, so the stage load(c+2) overwrites is free.
        __syncthreads();
        // 3) kick off chunk c+2 two stages ahead (overlaps compute of c, c+1)
        if (c + 2 < NCHUNK) {
            int s2 = stage + 2; if (s2 >= NSTAGE) s2 -= NSTAGE;
            load_chunk(sb + s2 * STAGE_BYTES, Ah, Al, Bh,
                       m0, n0, (c + 2) * BK, tid);
            CP_ASYNC_COMMIT();
        }

        const uint32_t base = sb + stage * STAGE_BYTES;
        const uint32_t aH = base + OFF_AH + rowAbyte;
        const uint32_t aL = base + OFF_AL + rowAbyte;
        const uint32_t bH = base + OFF_BH + rowBbyte;

        #pragma unroll
        for (int k16 = 0; k16 < 4; k16++) {
            const uint32_t colb = (uint32_t)((k16 * 32 + khalf) ^ xr);
            uint32_t ah[4][4], al[4][4];
            #pragma unroll
            for (int mt = 0; mt < 4; mt++) {
                ldsm4(ah[mt], aH + mt * 2048 + colb);
                ldsm4(al[mt], aL + mt * 2048 + colb);
            }
            #pragma unroll
            for (int nt = 0; nt < 4; nt++) {
                uint32_t b[4];
                ldsm4(b, bH + nt * 2048 + colb);
                // Ah pass then Al pass: dependent writes to the same
                // accumulator are spaced 8 MMAs apart
                #pragma unroll
                for (int mt = 0; mt < 4; mt++) {
                    mma16816(acc[mt][2 * nt],     ah[mt], b[0], b[2]);
                    mma16816(acc[mt][2 * nt + 1], ah[mt], b[1], b[3]);
                }
                #pragma unroll
                for (int mt = 0; mt < 4; mt++) {
                    mma16816(acc[mt][2 * nt],     al[mt], b[0], b[2]);
                    mma16816(acc[mt][2 * nt + 1], al[mt], b[1], b[3]);
                }
            }
        }
        if (++stage >= NSTAGE) stage = 0;
    }

    // epilogue: add bias, write fp32
    const int gr  = lane >> 2;
    const int cp2 = (lane & 3) * 2;
    #pragma unroll
    for (int n8 = 0; n8 < 8; n8++) {
        const int col = n0 + wn * 64 + n8 * 8 + cp2;
        const float2 bv = *(const float2*)(bias + col);
        #pragma unroll
        for (int mt = 0; mt < 4; mt++) {
            const int row = m0 + wm * 64 + mt * 16 + gr;
            float2 v0 = { acc[mt][n8][0] + bv.x, acc[mt][n8][1] + bv.y };
            float2 v1 = { acc[mt][n8][2] + bv.x, acc[mt][n8][3] + bv.y };
            *(float2*)(C + (size_t)row * N + col)       = v0;
            *(float2*)(C + (size_t)(row + 8) * N + col) = v1;
        }
    }
}

// ---------------------------------------------------------------------------
// fp32 -> (fp16 hi, fp16 lo) split, vectorized
// ---------------------------------------------------------------------------
__device__ __forceinline__ void split4h(const float4 v, uint2* uh, uint2* ul) {
    float f[4] = { v.x, v.y, v.z, v.w };
    unsigned short hs[4], ls[4];
    #pragma unroll
    for (int j = 0; j < 4; j++) {
        __half h = __float2half_rn(f[j]);
        __half l = __float2half_rn(f[j] - __half2float(h));
        hs[j] = __half_as_ushort(h);
        ls[j] = __half_as_ushort(l);
    }
    uh->x = (uint32_t)hs[0] | ((uint32_t)hs[1] << 16);
    uh->y = (uint32_t)hs[2] | ((uint32_t)hs[3] << 16);
    ul->x = (uint32_t)ls[0] | ((uint32_t)ls[1] << 16);
    ul->y = (uint32_t)ls[2] | ((uint32_t)ls[3] << 16);
}

__global__ void __launch_bounds__(256) split_x_fp16(
    const float* __restrict__ in,
    __half* __restrict__ hi, __half* __restrict__ lo, int n4)
{
    int i = blockIdx.x * blockDim.x + threadIdx.x;
    const int stride = gridDim.x * blockDim.x;
    for (; i < n4; i += stride) {
        uint2 uh, ul;
        split4h(((const float4*)in)[i], &uh, &ul);
        ((uint2*)hi)[i] = uh;
        ((uint2*)lo)[i] = ul;
    }
}

// fp32 -> fp16 (hi only), for weights
__device__ __forceinline__ uint2 cvt4h(const float4 v) {
    unsigned short hs[4] = {
        __half_as_ushort(__float2half_rn(v.x)),
        __half_as_ushort(__float2half_rn(v.y)),
        __half_as_ushort(__float2half_rn(v.z)),
        __half_as_ushort(__float2half_rn(v.w)) };
    uint2 u;
    u.x = (uint32_t)hs[0] | ((uint32_t)hs[1] << 16);
    u.y = (uint32_t)hs[2] | ((uint32_t)hs[3] << 16);
    return u;
}

// Fused convert of Wq/Wk/Wv into packed [3072,2048] fp16 + bias concat.
__global__ void __launch_bounds__(256) cvt_w1_fused(
    const float* __restrict__ Wq, const float* __restrict__ Wk,
    const float* __restrict__ Wv,
    const float* __restrict__ bq, const float* __restrict__ bk,
    const float* __restrict__ bv,
    __half* __restrict__ hi, float* __restrict__ b1)
{
    const int tid0 = blockIdx.x * blockDim.x + threadIdx.x;
    // bias concat: 3072 floats = 768 float4
    if (tid0 < 768) {
        float4 v;
        if      (tid0 < 512) v = ((const float4*)bq)[tid0];
        else if (tid0 < 640) v = ((const float4*)bk)[tid0 - 512];
        else                 v = ((const float4*)bv)[tid0 - 640];
        ((float4*)b1)[tid0] = v;
    }
    const int n4 = NQKV * (KDIM / 4);      // rows x 512 float4 per row
    const int stride = gridDim.x * blockDim.x;
    for (int i = tid0; i < n4; i += stride) {
        const int row = i >> 9;            // /512
        const int col = i & 511;
        float4 v;
        if      (row < 2048) v = ((const float4*)Wq)[(size_t)row * 512 + col];
        else if (row < 2560) v = ((const float4*)Wk)[(size_t)(row - 2048) * 512 + col];
        else                 v = ((const float4*)Wv)[(size_t)(row - 2560) * 512 + col];
        ((uint2*)hi)[i] = cvt4h(v);
    }
}

__global__ void __launch_bounds__(256) cvt_w_fp16(
    const float* __restrict__ in, __half* __restrict__ hi, int n4)
{
    int i = blockIdx.x * blockDim.x + threadIdx.x;
    const int stride = gridDim.x * blockDim.x;
    for (; i < n4; i += stride)
        ((uint2*)hi)[i] = cvt4h(((const float4*)in)[i]);
}

// ---------------------------------------------------------------------------
// Per-token attention. One block per token; q,k,v = one 3072-wide row of QKV
// (cols 0..2047 Q 16 heads, 2048..2559 K 4 heads, 2560..3071 V 4 heads).
// For q head r: s[kv] = q_r . k_kv / sqrt(128); softmax over 4 kv heads;
// out_r = sum w[kv] * v_kv. Output written pre-split into fp16 hi/lo.
// ---------------------------------------------------------------------------
__global__ void __launch_bounds__(128) attn_kernel(
    const float* __restrict__ QKV,
    __half* __restrict__ Ahi, __half* __restrict__ Alo)
{
    __shared__ float ks[512], vs[512];
    const int tok  = blockIdx.x;
    const int tid  = threadIdx.x;
    const int lane = tid & 31;
    const int w    = tid >> 5;
    const float* base = QKV + (size_t)tok * NQKV;

    ((float4*)ks)[tid] = ((const float4*)(base + 2048))[tid];
    ((float4*)vs)[tid] = ((const float4*)(base + 2560))[tid];
    __syncthreads();

    const float inv = 0.08838834764831845f;   // 1/sqrt(128)
    #pragma unroll
    for (int i = 0; i < 4; i++) {
        const int r = w * 4 + i;               // q head index 0..15
        float4 q4 = ((const float4*)(base + r * 128))[lane];
        float s[4];
        #pragma unroll
        for (int kv = 0; kv < 4; kv++) {
            float4 k4 = ((const float4*)(ks + kv * 128))[lane];
            float p = q4.x * k4.x + q4.y * k4.y + q4.z * k4.z + q4.w * k4.w;
            #pragma unroll
            for (int o = 16; o; o >>= 1) p += __shfl_xor_sync(0xffffffffu, p, o);
            s[kv] = p * inv;
        }
        float m = fmaxf(fmaxf(s[0], s[1]), fmaxf(s[2], s[3]));
        float e0 = __expf(s[0] - m), e1 = __expf(s[1] - m);
        float e2 = __expf(s[2] - m), e3 = __expf(s[3] - m);
        float rs = 1.0f / (e0 + e1 + e2 + e3);
        float w0 = e0 * rs, w1 = e1 * rs, w2 = e2 * rs, w3 = e3 * rs;

        float4 v0 = ((const float4*)(vs +   0))[lane];
        float4 v1 = ((const float4*)(vs + 128))[lane];
        float4 v2 = ((const float4*)(vs + 256))[lane];
        float4 v3 = ((const float4*)(vs + 384))[lane];
        float4 f;
        f.x = w0 * v0.x + w1 * v1.x + w2 * v2.x + w3 * v3.x;
        f.y = w0 * v0.y + w1 * v1.y + w2 * v2.y + w3 * v3.y;
        f.z = w0 * v0.z + w1 * v1.z + w2 * v2.z + w3 * v3.z;
        f.w = w0 * v0.w + w1 * v1.w + w2 * v2.w + w3 * v3.w;

        uint2 uh, ul;
        split4h(f, &uh, &ul);
        const size_t idx = (size_t)tok * KDIM + r * 128 + lane * 4;
        *(uint2*)(Ahi + idx) = uh;
        *(uint2*)(Alo + idx) = ul;
    }
}

// ---------------------------------------------------------------------------
// Host launcher
// ---------------------------------------------------------------------------
extern "C" void kernel_launch(void* const* d_in, const int* in_sizes, int n_in,
                              void* d_out, int out_size)
{
    (void)in_sizes; (void)n_in; (void)out_size;
    const float* x  = (const float*)d_in[0];
    const float* Wq = (const float*)d_in[1];
    const float* bq = (const float*)d_in[2];
    const float* Wk = (const float*)d_in[3];
    const float* bk = (const float*)d_in[4];
    const float* Wv = (const float*)d_in[5];
    const float* bv = (const float*)d_in[6];
    const float* Wo = (const float*)d_in[7];
    const float* bo = (const float*)d_in[8];

    void *p_xh, *p_xl, *p_w1h, *p_woh, *p_b1, *p_qkv, *p_ah, *p_al;
    cudaGetSymbolAddress(&p_xh,  g_Xhi);
    cudaGetSymbolAddress(&p_xl,  g_Xlo);
    cudaGetSymbolAddress(&p_w1h, g_W1hi);
    cudaGetSymbolAddress(&p_woh, g_Wohi);
    cudaGetSymbolAddress(&p_b1,  g_b1);
    cudaGetSymbolAddress(&p_qkv, g_QKV);
    cudaGetSymbolAddress(&p_ah,  g_Athi);
    cudaGetSymbolAddress(&p_al,  g_Atlo);

    __half* xh  = (__half*)p_xh;
    __half* xl  = (__half*)p_xl;
    __half* w1h = (__half*)p_w1h;
    __half* woh = (__half*)p_woh;
    float*  b1  = (float*)p_b1;
    float*  qkv = (float*)p_qkv;
    __half* ah  = (__half*)p_ah;
    __half* al  = (__half*)p_al;

    // launch order (gemm2 is launch 6 so ncu -s 5 -c 1 captures it):
    // 1 split_x, 2 cvt_w1_fused, 3 cvt_wo, 4 gemm1, 5 attn, 6 gemm2
    split_x_fp16<<<2048, 256>>>(x, xh, xl, TOK * KDIM / 4);
    cvt_w1_fused<<<512, 256>>>(Wq, Wk, Wv, bq, bk, bv, w1h, b1);
    cvt_w_fp16<<<256, 256>>>(Wo, woh, 2048 * 2048 / 4);

    cudaFuncSetAttribute(gemm_fp16x2,
                         cudaFuncAttributeMaxDynamicSharedMemorySize, SMEM_TOTAL);

    // GEMM1: QKV = X @ W1h^T + b1   (X applied exactly via hi+lo)
    gemm_fp16x2<<<dim3(NQKV / BN, TOK / BM), 256, SMEM_TOTAL>>>(
        xh, xl, w1h, b1, qkv, NQKV);

    // per-token attention -> fp16 hi/lo split output
    attn_kernel<<<TOK, 128>>>(qkv, ah, al);

    // GEMM2: out = Att @ Woh^T + bo
    gemm_fp16x2<<<dim3(NOUT / BN, TOK / BM), 256, SMEM_TOTAL>>>(
        ah, al, woh, bo, (float*)d_out, NOUT);
}